// round 16
// baseline (speedup 1.0000x reference)
#include <cuda_runtime.h>
#include <math.h>
#include <stdint.h>

// NuclearLattice: D=3, W=64 -> box [-32,32]^3, spin in [-0.5,0.5]
// V0=10, VS=2, A_RANGE=2, KC=1.44, EPS=1e-6, PAULI_D2=1e-6.
// gauss = exp(-d2/4) = ex2(d2n) with d2n = -CSCL*d2; d2 = d2n*KINV.
// Cutoff: tile pairs with positional gap^2 > 76 have negligible gauss
// (<=128^2*10.5*e^-19 ~ 0.01 abs vs |E|~2e5, tol 1e-3) and cannot pauli.

#define TPB  128
#define TILE 128
#define CAP  8192          // max A for the sorted path

#define CSCL 0.36067376f   // 0.25 * log2(e)
#define KINV (-2.7725887f) // -1/CSCL = -4*ln(2)
#define CUT2 76.0f

__device__ double       g_acc     = 0.0;
__device__ int          g_blocked = 0;
__device__ unsigned int g_done    = 0;

// binning scratch (static __device__: no allocs)
__device__ float4 g_raw[CAP];   // {x, y, z, psq}
__device__ float2 g_spq[CAP];   // {sp, q}
__device__ int    g_br[CAP];    // bin | (rank<<7)
__device__ int    g_hist[128];  // zero-init; re-zeroed by k_scatter each call

#define EX2(d, a) \
    asm("ex2.approx.f32 %0, %1;" : "=f"(d) : "f"(a))
#define RSQ(d, a) \
    asm("rsqrt.approx.f32 %0, %1;" : "=f"(d) : "f"(a))

// ---- K1: histogram + per-atom rank (bins = charge-class x x-slab) ----
__global__ void k_hist(const float* __restrict__ states, int A, int nb) {
    const int i = blockIdx.x * 256 + threadIdx.x;
    if (i >= A) return;
    const float* s = states + (size_t)i * 5;
    const float x = s[0];
    const float q = s[4] + 0.5f;
    int slab = (int)((x + 32.0f) * ((float)nb / 64.0f));
    slab = min(max(slab, 0), nb - 1);
    const int bin = ((q != 0.0f) ? nb : 0) + slab;
    const int r = atomicAdd(&g_hist[bin], 1);
    g_br[i] = bin | (r << 7);
}

// ---- K2: prefix over bins + scatter into sorted arrays + hist reset ----
__global__ void k_scatter(const float* __restrict__ states, int A) {
    __shared__ int sbase[128];
    const int t = threadIdx.x;
    if (t == 0) {
        int acc = 0;
        for (int b = 0; b < 128; b++) { sbase[b] = acc; acc += g_hist[b]; }
    }
    __syncthreads();
    if (t < 128) g_hist[t] = 0;     // reset for next graph replay
    for (int i = t; i < A; i += blockDim.x) {
        const float* s = states + (size_t)i * 5;
        const float x = s[0], y = s[1], z = s[2], sp = s[3];
        const float q = s[4] + 0.5f;
        const int br  = g_br[i];
        const int dst = sbase[br & 127] + (br >> 7);
        g_raw[dst] = make_float4(x, y, z, fmaf(x, x, fmaf(y, y, z * z)));
        g_spq[dst] = make_float2(sp, q);
    }
}

// ---- off-diag uniform fast path (2 chains; GAUSS/COUL/PAULI selectable) ----
template<bool COUL, bool PAULI, bool GAUSS>
__device__ __forceinline__ void fast_off(
    const float4* __restrict__ sa,      // {2C*x, 2C*y, 2C*z, -C*psq}
    float xi, float yi, float zi, float npsqi,
    float coef, float cq,
    float& acc0, float& acc1, float& pmax0, float& pmax1)
{
    #pragma unroll 8
    for (int p = 0; p < TILE / 2; p++) {
        const float4 a0 = sa[2 * p];
        const float4 a1 = sa[2 * p + 1];
        const float t0 = fmaf(a0.x, xi, fmaf(a0.y, yi, fmaf(a0.z, zi, a0.w))) + npsqi;
        const float t1 = fmaf(a1.x, xi, fmaf(a1.y, yi, fmaf(a1.z, zi, a1.w))) + npsqi;
        if (GAUSS) {
            float g0, g1;
            EX2(g0, t0);
            EX2(g1, t1);
            acc0 = fmaf(coef, g0, acc0);
            acc1 = fmaf(coef, g1, acc1);
        }
        if (COUL) {
            const float v0 = fmaxf(fmaf(t0, KINV, 1e-6f), 1e-6f);
            const float v1 = fmaxf(fmaf(t1, KINV, 1e-6f), 1e-6f);
            float r0, r1;
            RSQ(r0, v0);
            RSQ(r1, v1);
            acc0 = fmaf(cq, r0, acc0);
            acc1 = fmaf(cq, r1, acc1);
        }
        if (PAULI) {
            pmax0 = fmaxf(pmax0, t0);
            pmax1 = fmaxf(pmax1, t1);
        }
    }
}

// ---- diag fast path (uniform tile) ----
template<bool COUL>
__device__ __forceinline__ void fast_diag(
    const float4* __restrict__ sa,
    float xi, float yi, float zi, float npsqi,
    float coef, float cq, float thr, int tid, float& acc, int& pcount)
{
    #pragma unroll 8
    for (int jj = 0; jj < TILE; jj++) {
        const float4 a = sa[jj];
        const float d2n = fmaf(a.x, xi, fmaf(a.y, yi, fmaf(a.z, zi, a.w))) + npsqi;
        float g;
        EX2(g, d2n);
        float e = coef * g;
        if (COUL) {
            const float v = fmaxf(fmaf(d2n, KINV, 1e-6f), 1e-6f);
            float r;
            RSQ(r, v);
            e = fmaf(cq, r, e);
        }
        if (jj != tid) {                // exclude self pair
            acc += e;
            pcount += (d2n > thr) ? 1 : 0;
        }
    }
}

// ---- general fallback: exact per-pair spin/charge (any data) ----
template<bool DIAG>
__device__ __forceinline__ void gen_loop(
    const float4* __restrict__ sa,
    const float2* __restrict__ sb,
    float xi, float yi, float zi, float npsqi,
    float spi, float qi, int tid,
    float& acc, float& pmin, int& pcount)
{
    #pragma unroll 4
    for (int jj = 0; jj < TILE; jj++) {
        const float4 a = sa[jj];
        const float2 b = sb[jj];
        const float d2n = fmaf(a.x, xi, fmaf(a.y, yi, fmaf(a.z, zi, a.w))) + npsqi;
        const float d2  = fmaxf(d2n * KINV, 0.0f);
        const float dsp = spi - b.x;
        const float dq  = qi  - b.y;
        const float d2c = fmaf(dsp, dsp, fmaf(dq, dq, d2));
        float g;
        EX2(g, d2n);
        const float coef = fmaf(2.0f * spi, b.x, -10.0f);
        float r;
        RSQ(r, d2 + 1e-6f);
        const float cq = 1.44f * qi * b.y;
        const float e  = fmaf(coef, g, cq * r);
        if (DIAG) {
            if (jj != tid) { acc += e; pcount += (d2c < 1e-6f) ? 1 : 0; }
        } else {
            acc += e; pmin = fminf(pmin, d2c);
        }
    }
}

__global__ __launch_bounds__(TPB) void nl_kernel(
    const float* __restrict__ states, int A, int nblocks, int sorted,
    float* __restrict__ out)
{
    // Decode triangular block index k -> (bx <= by)
    const int k = blockIdx.x;
    int by = (int)((sqrtf(8.0f * (float)k + 1.0f) - 1.0f) * 0.5f);
    while ((by + 1) * (by + 2) / 2 <= k) by++;
    while (by * (by + 1) / 2 > k)       by--;
    const int bx = k - by * (by + 1) / 2;
    const bool diag = (bx == by);

    __shared__ float4 sa[TILE];
    __shared__ float2 sb[TILE];
    __shared__ float4 uref;             // {sp_i0, q_i0, sp_j0, q_j0}
    __shared__ float  sred[6][4];       // {ixmin,ixmax,jxmin,jxmax,aqi,aqj} x 4 warps

    const int tid  = threadIdx.x;
    const int lane = tid & 31;
    const int warp = tid >> 5;

    // ---- i-atom ----
    const int i = bx * TILE + tid;
    const bool vi = (i < A);
    float xi = 1e18f, yi = 1e18f, zi = 1e18f, psqi = 1e36f, spi = 0.0f, qi = 0.0f;
    if (vi) {
        if (sorted) {
            const float4 R = g_raw[i];
            const float2 P = g_spq[i];
            xi = R.x; yi = R.y; zi = R.z; psqi = R.w; spi = P.x; qi = P.y;
        } else {
            const float* s = states + (size_t)i * 5;
            xi = s[0]; yi = s[1]; zi = s[2]; spi = s[3]; qi = s[4] + 0.5f;
            psqi = fmaf(xi, xi, fmaf(yi, yi, zi * zi));
        }
    }
    const float npsqi = -CSCL * psqi;

    // bounds check once per atom (each atom in exactly one diag block)
    if (diag && vi) {
        const bool bad = (xi  < -32.0f) || (xi  > 32.0f) ||
                         (yi  < -32.0f) || (yi  > 32.0f) ||
                         (zi  < -32.0f) || (zi  > 32.0f) ||
                         (spi < -0.5f)  || (spi > 0.5f);
        if (bad) atomicOr(&g_blocked, 1);
    }

    // ---- j-tile -> smem ----
    const int j = by * TILE + tid;
    const bool vj = (j < A);
    float jx = -1e18f, jsp = 0.0f, jq = 0.0f;
    {
        float x = -1e18f, y = -1e18f, z = -1e18f, psq = 1e36f;
        if (vj) {
            if (sorted) {
                const float4 R = g_raw[j];
                const float2 P = g_spq[j];
                x = R.x; y = R.y; z = R.z; psq = R.w; jsp = P.x; jq = P.y;
            } else {
                const float* s = states + (size_t)j * 5;
                x = s[0]; y = s[1]; z = s[2]; jsp = s[3]; jq = s[4] + 0.5f;
                psq = fmaf(x, x, fmaf(y, y, z * z));
            }
        }
        jx = x;
        sa[tid] = make_float4(2.0f * CSCL * x, 2.0f * CSCL * y,
                              2.0f * CSCL * z, -CSCL * psq);
        sb[tid] = make_float2(jsp, jq);
    }
    if (tid == 0) uref = make_float4(spi, qi, jsp, jq);

    // ---- 6 block reductions (warp shuffle; one shared barrier) ----
    {
        float v0 = vi ? xi : 1e30f;           // ixmin
        float v1 = vi ? xi : -1e30f;          // ixmax
        float v2 = vj ? jx : 1e30f;           // jxmin
        float v3 = vj ? jx : -1e30f;          // jxmax
        float v4 = vi ? fabsf(qi) : 0.0f;     // aqi
        float v5 = vj ? fabsf(jq) : 0.0f;     // aqj
        #pragma unroll
        for (int o = 16; o > 0; o >>= 1) {
            v0 = fminf(v0, __shfl_xor_sync(0xffffffffu, v0, o));
            v1 = fmaxf(v1, __shfl_xor_sync(0xffffffffu, v1, o));
            v2 = fminf(v2, __shfl_xor_sync(0xffffffffu, v2, o));
            v3 = fmaxf(v3, __shfl_xor_sync(0xffffffffu, v3, o));
            v4 = fmaxf(v4, __shfl_xor_sync(0xffffffffu, v4, o));
            v5 = fmaxf(v5, __shfl_xor_sync(0xffffffffu, v5, o));
        }
        if (lane == 0) {
            sred[0][warp] = v0; sred[1][warp] = v1; sred[2][warp] = v2;
            sred[3][warp] = v3; sred[4][warp] = v4; sred[5][warp] = v5;
        }
    }
    __syncthreads();   // publishes sa, sb, uref, sred

    const float ixmin = fminf(fminf(sred[0][0], sred[0][1]), fminf(sred[0][2], sred[0][3]));
    const float ixmax = fmaxf(fmaxf(sred[1][0], sred[1][1]), fmaxf(sred[1][2], sred[1][3]));
    const float jxmin = fminf(fminf(sred[2][0], sred[2][1]), fminf(sred[2][2], sred[2][3]));
    const float jxmax = fmaxf(fmaxf(sred[3][0], sred[3][1]), fmaxf(sred[3][2], sred[3][3]));
    const float aqi   = fmaxf(fmaxf(sred[4][0], sred[4][1]), fmaxf(sred[4][2], sred[4][3]));
    const float aqj   = fmaxf(fmaxf(sred[5][0], sred[5][1]), fmaxf(sred[5][2], sred[5][3]));

    const float gap = fmaxf(fmaxf(jxmin - ixmax, ixmin - jxmax), 0.0f);
    const bool  far = (!diag) && (gap * gap > CUT2);   // gauss+pauli negligible
    const bool  coulpair = (aqi > 0.0f) && (aqj > 0.0f);

    // tile-pair uniformity: all valid atoms match the first atom of their tile
    bool myuni = (!vi || (spi == uref.x && qi == uref.y)) &&
                 (!vj || (jsp == uref.z && jq == uref.w));
    const int unified = __syncthreads_and(myuni ? 1 : 0);

    float acc    = 0.0f;
    float accB   = 0.0f;
    float pmaxA  = -1e30f, pmaxB = -1e30f;
    float pmin   = 1e30f;
    int   pcount = 0;
    bool  pauli  = false;

    if (far && !coulpair) {
        // fully skippable tile pair: contributes nothing
    } else if (far && coulpair && unified) {
        // coulomb-only (no gauss, no pauli possible at gap^2 > CUT2)
        const float cq = 1.44f * uref.y * uref.w;
        fast_off<true, false, false>(sa, xi, yi, zi, npsqi, 0.0f, cq,
                                     acc, accB, pmaxA, pmaxB);
        acc += accB;
    } else if (unified) {
        const float coef = fmaf(2.0f * uref.x, uref.z, -10.0f);
        const float cq   = 1.44f * uref.y * uref.w;
        const float dsp  = uref.x - uref.z;
        const float dq   = uref.y - uref.w;
        const float dcc  = fmaf(dsp, dsp, dq * dq);
        const bool  coul = (cq != 0.0f);
        const bool  pact = (dcc < 1e-6f);
        const float thr  = -(1e-6f - dcc) * CSCL;   // d2n > thr <=> d2+dcc < 1e-6

        if (diag) {
            if (coul) fast_diag<true >(sa, xi, yi, zi, npsqi, coef, cq, thr, tid, acc, pcount);
            else      fast_diag<false>(sa, xi, yi, zi, npsqi, coef, cq, thr, tid, acc, pcount);
            pauli = (pcount > 0);
        } else {
            if      ( coul &&  pact) fast_off<true,  true,  true>(sa, xi, yi, zi, npsqi, coef, cq, acc, accB, pmaxA, pmaxB);
            else if ( coul && !pact) fast_off<true,  false, true>(sa, xi, yi, zi, npsqi, coef, cq, acc, accB, pmaxA, pmaxB);
            else if (!coul &&  pact) fast_off<false, true,  true>(sa, xi, yi, zi, npsqi, coef, cq, acc, accB, pmaxA, pmaxB);
            else                     fast_off<false, false, true>(sa, xi, yi, zi, npsqi, coef, cq, acc, accB, pmaxA, pmaxB);
            acc += accB;
            pauli = pact && (fmaxf(pmaxA, pmaxB) > thr);
        }
    } else {
        if (diag) {
            gen_loop<true >(sa, sb, xi, yi, zi, npsqi, spi, qi, tid, acc, pmin, pcount);
            pauli = (pcount > 0);
        } else {
            gen_loop<false>(sa, sb, xi, yi, zi, npsqi, spi, qi, tid, acc, pmin, pcount);
            pauli = (pmin < 1e-6f);
        }
    }

    if (diag) acc *= 0.5f;              // diag tiles counted both orders
    if (pauli) atomicOr(&g_blocked, 1);

    // fp32 per-thread -> double warp -> block -> one atomic
    double v = (double)acc;
    #pragma unroll
    for (int off = 16; off > 0; off >>= 1)
        v += __shfl_down_sync(0xffffffffu, v, off);

    __shared__ double wsum[TPB / 32];
    if (lane == 0) wsum[warp] = v;
    __syncthreads();

    if (tid == 0) {
        v = wsum[0] + wsum[1] + wsum[2] + wsum[3];
        atomicAdd(&g_acc, v);
        __threadfence();
        const unsigned t = atomicAdd(&g_done, 1u);
        if (t == (unsigned)nblocks - 1u) {
            const double e  = atomicAdd(&g_acc, 0.0);
            const int    bl = atomicOr(&g_blocked, 0);
            out[0] = bl ? INFINITY : (float)e;
            g_acc     = 0.0;
            g_blocked = 0;
            __threadfence();
            g_done = 0;
        }
    }
}

extern "C" void kernel_launch(void* const* d_in, const int* in_sizes, int n_in,
                              void* d_out, int out_size) {
    const float* states = (const float*)d_in[0];
    const int A = in_sizes[0] / 5;

    const int tiles   = (A + TILE - 1) / TILE;
    const int nblocks = tiles * (tiles + 1) / 2;

    if (A <= CAP) {
        int nb = A / 128;                   // slabs per charge class
        if (nb < 1)  nb = 1;
        if (nb > 48) nb = 48;               // 2*nb <= 96 bins < 128
        k_hist<<<(A + 255) / 256, 256>>>(states, A, nb);
        k_scatter<<<1, 1024>>>(states, A);
        nl_kernel<<<nblocks, TPB>>>(states, A, nblocks, 1, (float*)d_out);
    } else {
        nl_kernel<<<nblocks, TPB>>>(states, A, nblocks, 0, (float*)d_out);
    }
}

// round 17
// speedup vs baseline: 1.7111x; 1.7111x over previous
#include <cuda_runtime.h>
#include <math.h>
#include <stdint.h>

// NuclearLattice: D=3, W=64 -> box [-32,32]^3, spin in [-0.5,0.5]
// V0=10, VS=2, A_RANGE=2, KC=1.44, EPS=1e-6, PAULI_D2=1e-6.
// gauss = exp(-d2/4) = ex2(d2n) with d2n = -CSCL*d2; d2 = d2n*KINV.

#define TPB  128
#define TILE 128

#define CSCL 0.36067376f     // 0.25 * log2(e)
#define KINV (-2.7725887f)   // -1/CSCL = -4*ln(2)

__device__ double       g_acc     = 0.0;
__device__ int          g_blocked = 0;
__device__ unsigned int g_done    = 0;

typedef unsigned long long u64;

#define PK2(v, lo, hi) \
    asm("mov.b64 %0, {%1, %2};" : "=l"(v) : "f"(lo), "f"(hi))
#define UNPK2(lo, hi, v) \
    asm("mov.b64 {%0, %1}, %2;" : "=f"(lo), "=f"(hi) : "l"(v))
#define FMA2(d, a, b, c) \
    asm("fma.rn.f32x2 %0, %1, %2, %3;" : "=l"(d) : "l"(a), "l"(b), "l"(c))
#define ADD2(d, a, b) \
    asm("add.rn.f32x2 %0, %1, %2;" : "=l"(d) : "l"(a), "l"(b))
#define EX2(d, a) \
    asm("ex2.approx.f32 %0, %1;" : "=f"(d) : "f"(a))
#define RSQ(d, a) \
    asm("rsqrt.approx.f32 %0, %1;" : "=f"(d) : "f"(a))

// ---- packed fast path (off-diag, uniform tile pair): 2 j-atoms per iter ----
// smem layout (16B per j-pair, two banks 1024B apart):
//   [addr]      = {x2c_j0, x2c_j1, y2c_j0, y2c_j1}
//   [addr+1024] = {z2c_j0, z2c_j1, w_j0,   w_j1}
// where x2c = 2*CSCL*x, w = -CSCL*psq.  d2n = dot-chain + npsqi = -CSCL*d2.
template<bool COUL, bool PAULI>
__device__ __forceinline__ void fast_off_packed(
    uint32_t sbase,
    u64 xi2, u64 yi2, u64 zi2, u64 npsq2,
    float coef, float cq,
    float& accA, float& accB, float& pmaxA, float& pmaxB)
{
    u64 kinv2, eps2;
    PK2(kinv2, KINV, KINV);
    PK2(eps2, 1e-6f, 1e-6f);

    #pragma unroll 8
    for (int p = 0; p < TILE / 2; p++) {
        const uint32_t addr = sbase + p * 16;
        u64 axy0, axy1, azw0, azw1;
        asm volatile("ld.shared.v2.b64 {%0, %1}, [%2];"
                     : "=l"(axy0), "=l"(axy1) : "r"(addr));
        asm volatile("ld.shared.v2.b64 {%0, %1}, [%2+1024];"
                     : "=l"(azw0), "=l"(azw1) : "r"(addr));

        u64 t;
        FMA2(t, azw0, zi2, azw1);     // z*zi + w
        FMA2(t, axy1, yi2, t);        // + y*yi
        FMA2(t, axy0, xi2, t);        // + x*xi
        ADD2(t, t, npsq2);            // + npsqi  -> d2n pair

        float d0, d1;
        UNPK2(d0, d1, t);

        float g0, g1;
        EX2(g0, d0);
        EX2(g1, d1);
        accA = fmaf(coef, g0, accA);
        accB = fmaf(coef, g1, accB);

        if (COUL) {
            u64 v;
            FMA2(v, t, kinv2, eps2);  // d2 + eps (clamped below)
            float v0, v1;
            UNPK2(v0, v1, v);
            v0 = fmaxf(v0, 1e-6f);
            v1 = fmaxf(v1, 1e-6f);
            float r0, r1;
            RSQ(r0, v0);
            RSQ(r1, v1);
            accA = fmaf(cq, r0, accA);
            accB = fmaf(cq, r1, accB);
        }
        if (PAULI) {
            pmaxA = fmaxf(pmaxA, d0);
            pmaxB = fmaxf(pmaxB, d1);
        }
    }
}

// ---- scalar diag fast path (uniform tile) ----
template<bool COUL>
__device__ __forceinline__ void fast_diag(
    const float4* __restrict__ sa,
    float xi, float yi, float zi, float npsqi,
    float coef, float cq, float thr, int tid, float& acc, int& pcount)
{
    #pragma unroll 8
    for (int jj = 0; jj < TILE; jj++) {
        const float4 a = sa[jj];
        const float d2n = fmaf(a.x, xi, fmaf(a.y, yi, fmaf(a.z, zi, a.w))) + npsqi;
        float g;
        EX2(g, d2n);
        float e = coef * g;
        if (COUL) {
            const float v = fmaxf(fmaf(d2n, KINV, 1e-6f), 1e-6f);
            float r;
            RSQ(r, v);
            e = fmaf(cq, r, e);
        }
        if (jj != tid) {                        // exclude self pair
            acc += e;
            pcount += (d2n > thr) ? 1 : 0;
        }
    }
}

// ---- general fallback: exact per-pair spin/charge (any data) ----
template<bool DIAG>
__device__ __forceinline__ void gen_loop(
    const float4* __restrict__ sa,
    const float2* __restrict__ sb,              // {sp, q}
    float xi, float yi, float zi, float npsqi,
    float spi, float qi, int tid,
    float& acc, float& pmin, int& pcount)
{
    #pragma unroll 4
    for (int jj = 0; jj < TILE; jj++) {
        const float4 a = sa[jj];
        const float2 b = sb[jj];
        const float d2n = fmaf(a.x, xi, fmaf(a.y, yi, fmaf(a.z, zi, a.w))) + npsqi;
        const float d2  = fmaxf(d2n * KINV, 0.0f);
        const float dsp = spi - b.x;
        const float dq  = qi  - b.y;
        const float d2c = fmaf(dsp, dsp, fmaf(dq, dq, d2));
        float g;
        EX2(g, d2n);
        const float coef = fmaf(2.0f * spi, b.x, -10.0f);
        float r;
        RSQ(r, d2 + 1e-6f);
        const float cq = 1.44f * qi * b.y;
        const float e  = fmaf(coef, g, cq * r);
        if (DIAG) {
            if (jj != tid) { acc += e; pcount += (d2c < 1e-6f) ? 1 : 0; }
        } else {
            acc += e; pmin = fminf(pmin, d2c);
        }
    }
}

__global__ __launch_bounds__(TPB) void nl_kernel(
    const float* __restrict__ states, int A, int nblocks, float* __restrict__ out)
{
    // Decode triangular block index k -> (bx <= by)
    const int k = blockIdx.x;
    int by = (int)((sqrtf(8.0f * (float)k + 1.0f) - 1.0f) * 0.5f);
    while ((by + 1) * (by + 2) / 2 <= k) by++;
    while (by * (by + 1) / 2 > k)       by--;
    const int bx = k - by * (by + 1) / 2;
    const bool diag = (bx == by);

    __shared__ float4 sa[TILE];          // scalar layout (diag + fallback)
    __shared__ float4 spk[2][TILE / 2];  // packed layout (off-diag fast path)
    __shared__ float2 sb[TILE];
    __shared__ float4 uref;              // {sp_i0, q_i0, sp_j0, q_j0}

    const int tid = threadIdx.x;

    // i-atom; padding far away with zero spin/charge
    const int i = bx * TILE + tid;
    const bool vi = (i < A);
    float xi = 1e18f, yi = 1e18f, zi = 1e18f, spi = 0.0f, qi = 0.0f;
    if (vi) {
        const float* s = states + (size_t)i * 5;
        xi = s[0]; yi = s[1]; zi = s[2]; spi = s[3]; qi = s[4] + 0.5f;
    }
    const float npsqi = -CSCL * fmaf(xi, xi, fmaf(yi, yi, zi * zi));

    // bounds check once per atom (each atom appears in exactly one diag block)
    if (diag && vi) {
        const bool bad = (xi  < -32.0f) || (xi  > 32.0f) ||
                         (yi  < -32.0f) || (yi  > 32.0f) ||
                         (zi  < -32.0f) || (zi  > 32.0f) ||
                         (spi < -0.5f)  || (spi > 0.5f);
        if (bad) atomicOr(&g_blocked, 1);
    }

    // j-tile -> smem (both layouts); keep j (sp,q) in regs for uniformity check
    const int j = by * TILE + tid;
    const bool vj = (j < A);
    float jsp = 0.0f, jq = 0.0f;
    {
        float x = -1e18f, y = -1e18f, z = -1e18f;
        if (vj) {
            const float* s = states + (size_t)j * 5;
            x = s[0]; y = s[1]; z = s[2]; jsp = s[3]; jq = s[4] + 0.5f;
        }
        const float psq = fmaf(x, x, fmaf(y, y, z * z));
        const float x2c = 2.0f * CSCL * x;
        const float y2c = 2.0f * CSCL * y;
        const float z2c = 2.0f * CSCL * z;
        const float w   = -CSCL * psq;
        sa[tid] = make_float4(x2c, y2c, z2c, w);
        sb[tid] = make_float2(jsp, jq);
        // packed: pair p = tid>>1, half h = tid&1
        float* P = (float*)spk;
        const int p = tid >> 1, h = tid & 1;
        P[p * 4 + h]                = x2c;
        P[p * 4 + 2 + h]            = y2c;
        P[2 * TILE + p * 4 + h]     = z2c;
        P[2 * TILE + p * 4 + 2 + h] = w;
    }
    if (tid == 0) uref = make_float4(spi, qi, jsp, jq);
    __syncthreads();

    // tile-pair uniformity: all valid atoms match the first atom of their tile
    bool myuni = (!vi || (spi == uref.x && qi == uref.y)) &&
                 (!vj || (jsp == uref.z && jq == uref.w));
    const int unified = __syncthreads_and(myuni ? 1 : 0);

    float acc    = 0.0f;
    float accB   = 0.0f;
    float pmaxA  = -1e30f, pmaxB = -1e30f;
    float pmin   = 1e30f;
    int   pcount = 0;
    bool  pauli  = false;

    if (unified) {
        const float coef = fmaf(2.0f * uref.x, uref.z, -10.0f);  // -V0 + VS*sp_i*sp_j
        const float cq   = 1.44f * uref.y * uref.w;              // KC*q_i*q_j
        const float dsp  = uref.x - uref.z;
        const float dq   = uref.y - uref.w;
        const float dcc  = fmaf(dsp, dsp, dq * dq);
        const bool  coul = (cq != 0.0f);
        const bool  pact = (dcc < 1e-6f);                        // pauli possible at all
        const float thr  = -(1e-6f - dcc) * CSCL;                // d2n > thr <=> d2+dcc < 1e-6

        if (diag) {
            if (coul) fast_diag<true >(sa, xi, yi, zi, npsqi, coef, cq, thr, tid, acc, pcount);
            else      fast_diag<false>(sa, xi, yi, zi, npsqi, coef, cq, thr, tid, acc, pcount);
            pauli = (pcount > 0);
        } else {
            const uint32_t sbase = (uint32_t)__cvta_generic_to_shared(spk);
            u64 xi2, yi2, zi2, npsq2;
            PK2(xi2, xi, xi);
            PK2(yi2, yi, yi);
            PK2(zi2, zi, zi);
            PK2(npsq2, npsqi, npsqi);
            if      ( coul &&  pact) fast_off_packed<true,  true >(sbase, xi2, yi2, zi2, npsq2, coef, cq, acc, accB, pmaxA, pmaxB);
            else if ( coul && !pact) fast_off_packed<true,  false>(sbase, xi2, yi2, zi2, npsq2, coef, cq, acc, accB, pmaxA, pmaxB);
            else if (!coul &&  pact) fast_off_packed<false, true >(sbase, xi2, yi2, zi2, npsq2, coef, cq, acc, accB, pmaxA, pmaxB);
            else                     fast_off_packed<false, false>(sbase, xi2, yi2, zi2, npsq2, coef, cq, acc, accB, pmaxA, pmaxB);
            acc += accB;
            pauli = pact && (fmaxf(pmaxA, pmaxB) > thr);
        }
    } else {
        if (diag) {
            gen_loop<true >(sa, sb, xi, yi, zi, npsqi, spi, qi, tid, acc, pmin, pcount);
            pauli = (pcount > 0);
        } else {
            gen_loop<false>(sa, sb, xi, yi, zi, npsqi, spi, qi, tid, acc, pmin, pcount);
            pauli = (pmin < 1e-6f);
        }
    }

    if (diag) acc *= 0.5f;                  // diag tiles counted both orders
    if (pauli) atomicOr(&g_blocked, 1);

    // fp32 per-thread -> double warp -> block (4 warps) -> one atomic
    double v = (double)acc;
    #pragma unroll
    for (int off = 16; off > 0; off >>= 1)
        v += __shfl_down_sync(0xffffffffu, v, off);

    __shared__ double wsum[TPB / 32];
    const int lane = tid & 31;
    const int warp = tid >> 5;
    if (lane == 0) wsum[warp] = v;
    __syncthreads();

    if (tid == 0) {
        v = wsum[0] + wsum[1] + wsum[2] + wsum[3];
        atomicAdd(&g_acc, v);
        __threadfence();
        const unsigned t = atomicAdd(&g_done, 1u);
        if (t == (unsigned)nblocks - 1u) {
            // Last block: publish result and reset state for next graph replay
            const double e  = atomicAdd(&g_acc, 0.0);
            const int    bl = atomicOr(&g_blocked, 0);
            out[0] = bl ? INFINITY : (float)e;
            g_acc     = 0.0;
            g_blocked = 0;
            __threadfence();
            g_done = 0;
        }
    }
}

extern "C" void kernel_launch(void* const* d_in, const int* in_sizes, int n_in,
                              void* d_out, int out_size) {
    const float* states = (const float*)d_in[0];
    const int A = in_sizes[0] / 5;

    const int tiles   = (A + TILE - 1) / TILE;
    const int nblocks = tiles * (tiles + 1) / 2;

    nl_kernel<<<nblocks, TPB>>>(states, A, nblocks, (float*)d_out);
}